// round 4
// baseline (speedup 1.0000x reference)
#include <cuda_runtime.h>
#include <cuda_bf16.h>
#include <cstdint>

// ---------------------------------------------------------------------------
// Problem constants
// ---------------------------------------------------------------------------
#define BB   2
#define NPTS 100000
#define RES  256
#define CIN_ 64
#define COUT_ 128

// d_out layout: [out_pool | before_pool | x_after | c]
#define OFF_POOL   0
#define SZ_POOL    (2*128*128*128)            // 4,194,304
#define OFF_BP     (SZ_POOL)
#define SZ_BP      (2*128*256*256)            // 16,777,216
#define OFF_XAFTER (OFF_BP + SZ_BP)
#define OFF_C      (OFF_XAFTER + SZ_BP)

typedef unsigned long long u64;

// ---- packed f32x2 helpers (Blackwell FFMA2) -------------------------------
__device__ __forceinline__ u64 pack2(float lo, float hi) {
    u64 r;
    asm("mov.b64 %0, {%1, %2};" : "=l"(r)
        : "r"(__float_as_uint(lo)), "r"(__float_as_uint(hi)));
    return r;
}
__device__ __forceinline__ void unpack2(u64 v, float& lo, float& hi) {
    unsigned int a, b;
    asm("mov.b64 {%0, %1}, %2;" : "=r"(a), "=r"(b) : "l"(v));
    lo = __uint_as_float(a); hi = __uint_as_float(b);
}
__device__ __forceinline__ void fma2(u64& d, u64 a, u64 b) {
    asm("fma.rn.f32x2 %0, %1, %2, %0;" : "+l"(d) : "l"(a), "l"(b));
}

// ---------------------------------------------------------------------------
// Scratch (device globals; allocation-free)
// ---------------------------------------------------------------------------
__device__ float g_h1[2*128*256*256];     // conv1 output (NCHW)
__device__ float g_featT[2*256*256*128];  // x_after transposed (NHWC) for gather
__device__ float g_sums[2*256*256*128];   // scatter sums [b][seg][ch]
__device__ float g_cnt[2*256*256];        // scatter counts

// ---------------------------------------------------------------------------
__global__ void zero_kernel(float* a, int n4) {
    int i = blockIdx.x * blockDim.x + threadIdx.x;
    if (i < n4) ((float4*)a)[i] = make_float4(0.f, 0.f, 0.f, 0.f);
}

// ---------------------------------------------------------------------------
// 3x3 conv, pad 1, 256x256, COUT=128. Block: 256 thr, 32x32 px tile, 8 ocs.
// f32x2: accumulators packed over oc-pairs (4 pairs) x 4 pixels.
// Weights transposed in smem to [k][9][8oc] so oc-pairs are natural u64 loads.
// FUSE: += 1x1 conv of x2 (packed too) and write NHWC copy for sampler.
// ---------------------------------------------------------------------------
template<int CIN, bool FUSE>
__global__ __launch_bounds__(256)
void conv3x3_kernel(const float* __restrict__ in, const float* __restrict__ w,
                    const float* __restrict__ bias,
                    const float* __restrict__ x2, const float* __restrict__ w1x1,
                    const float* __restrict__ b1x1,
                    float* __restrict__ out_nchw, float* __restrict__ out_nhwc)
{
    __shared__ __align__(16) float s_w2[CIN*72];       // [k][9][8oc]
    __shared__ __align__(16) float s_in[2*1160];       // 2 channels, 34x34 each
    __shared__ __align__(16) float s_w1t[FUSE ? 64*8 : 8];  // [k][8oc]

    const int tid = threadIdx.x;
    const int bz  = blockIdx.z;
    const int b   = bz >> 4;
    const int ocg = bz & 15;
    const int gx0 = blockIdx.x * 32;
    const int gy0 = blockIdx.y * 32;
    const int tx  = tid & 31;
    const int yg  = tid >> 5;
    const int ly  = yg * 4;

    {   // preload + transpose weights: w[(ocg*8+o)*CIN*9 + k*9 + j] -> s_w2[(k*9+j)*8+o]
        const float* wsrc = w + (size_t)ocg * 8 * CIN * 9;
        for (int i = tid; i < 8*CIN*9; i += 256) {
            int o = i / (CIN*9);
            int rem = i - o * (CIN*9);
            s_w2[rem*8 + o] = wsrc[i];
        }
        if (FUSE) {
            for (int i = tid; i < 8*64; i += 256) {
                int o = i >> 6, k = i & 63;
                s_w1t[k*8 + o] = w1x1[(ocg*8 + o)*64 + k];
            }
        }
    }

    u64 acc[4][4];   // [oc-pair][pixel-row]
#pragma unroll
    for (int o2 = 0; o2 < 4; o2++)
#pragma unroll
        for (int r = 0; r < 4; r++) acc[o2][r] = 0ULL;

    for (int k0 = 0; k0 < CIN; k0 += 2) {
        __syncthreads();
#pragma unroll
        for (int c = 0; c < 2; c++) {
            const float* inp = in + (((size_t)b * CIN + k0 + c) << 16);
            float* sd = s_in + c * 1160;
            for (int i = tid; i < 34*34; i += 256) {
                int rr = i / 34;
                int cc = i - rr * 34;
                int y = gy0 - 1 + rr;
                int x = gx0 - 1 + cc;
                sd[i] = (y >= 0 && y < 256 && x >= 0 && x < 256)
                        ? inp[(y << 8) + x] : 0.f;
            }
        }
        __syncthreads();

#pragma unroll
        for (int kh = 0; kh < 2; kh++) {
            const float* si = s_in + kh * 1160;
            u64 vv[6][3];
#pragma unroll
            for (int rr = 0; rr < 6; rr++)
#pragma unroll
                for (int dx = 0; dx < 3; dx++) {
                    float v = si[(ly + rr) * 34 + tx + dx];
                    vv[rr][dx] = pack2(v, v);
                }
            const float* wbase = s_w2 + (k0 + kh) * 72;
#pragma unroll
            for (int j9 = 0; j9 < 9; j9++) {
                const int dy = j9 / 3, dx = j9 % 3;
                ulonglong2 wA = *(const ulonglong2*)(wbase + j9*8);     // oc pairs 0,1
                ulonglong2 wB = *(const ulonglong2*)(wbase + j9*8 + 4); // oc pairs 2,3
#pragma unroll
                for (int r = 0; r < 4; r++) {
                    u64 v = vv[r + dy][dx];
                    fma2(acc[0][r], v, wA.x);
                    fma2(acc[1][r], v, wA.y);
                    fma2(acc[2][r], v, wB.x);
                    fma2(acc[3][r], v, wB.y);
                }
            }
        }
    }

    // unpack, bias + relu
    float a8[8][4];
#pragma unroll
    for (int o2 = 0; o2 < 4; o2++)
#pragma unroll
        for (int r = 0; r < 4; r++)
            unpack2(acc[o2][r], a8[2*o2][r], a8[2*o2+1][r]);
#pragma unroll
    for (int o = 0; o < 8; o++) {
        float bb = bias[ocg*8 + o];
#pragma unroll
        for (int r = 0; r < 4; r++) a8[o][r] = fmaxf(a8[o][r] + bb, 0.f);
    }

    const int gy = gy0 + ly;

    if (FUSE) {   // += conv1x1(x2) + b1x1 (after relu, per reference)
        u64 acc1[4][4];
#pragma unroll
        for (int o2 = 0; o2 < 4; o2++)
#pragma unroll
            for (int r = 0; r < 4; r++) acc1[o2][r] = 0ULL;

        for (int k = 0; k < 64; k++) {
            const float* xp = x2 + (((size_t)b * 64 + k) << 16) + gx0 + tx;
            ulonglong2 wA = *(const ulonglong2*)(s_w1t + k*8);
            ulonglong2 wB = *(const ulonglong2*)(s_w1t + k*8 + 4);
#pragma unroll
            for (int r = 0; r < 4; r++) {
                float xv = __ldg(xp + ((size_t)(gy + r) << 8));
                u64 x2v = pack2(xv, xv);
                fma2(acc1[0][r], x2v, wA.x);
                fma2(acc1[1][r], x2v, wA.y);
                fma2(acc1[2][r], x2v, wB.x);
                fma2(acc1[3][r], x2v, wB.y);
            }
        }
#pragma unroll
        for (int o2 = 0; o2 < 4; o2++)
#pragma unroll
            for (int r = 0; r < 4; r++) {
                float lo, hi;
                unpack2(acc1[o2][r], lo, hi);
                a8[2*o2][r]   += lo;
                a8[2*o2+1][r] += hi;
            }
#pragma unroll
        for (int o = 0; o < 8; o++) {
            float bb = b1x1[ocg*8 + o];
#pragma unroll
            for (int r = 0; r < 4; r++) a8[o][r] += bb;
        }
    }

    // NCHW write
#pragma unroll
    for (int o = 0; o < 8; o++) {
        int oc = ocg*8 + o;
        float* op = out_nchw + (((size_t)b * 128 + oc) << 16) + gx0 + tx;
#pragma unroll
        for (int r = 0; r < 4; r++) op[(size_t)(gy + r) << 8] = a8[o][r];
    }
    // NHWC write (feature map for sampler)
    if (FUSE) {
#pragma unroll
        for (int r = 0; r < 4; r++) {
            float4 v0 = make_float4(a8[0][r], a8[1][r], a8[2][r], a8[3][r]);
            float4 v1 = make_float4(a8[4][r], a8[5][r], a8[6][r], a8[7][r]);
            float* tp = out_nhwc +
                ((((size_t)b << 16) + ((size_t)(gy + r) << 8) + gx0 + tx) << 7) + ocg * 8;
            ((float4*)tp)[0] = v0;
            ((float4*)tp)[1] = v1;
        }
    }
}

// ---------------------------------------------------------------------------
// Point kernel: 64 points per block, 256 threads.  f32x2 packed over row-pairs.
// ---------------------------------------------------------------------------
#define SA_STRIDE 132
#define SH_STRIDE 260
#define SCL_STRIDE 68
#define PK_SMEM_FLOATS (64*SA_STRIDE + 64*SH_STRIDE + 4096 + 64*SCL_STRIDE)

__global__ __launch_bounds__(256, 1)
void point_kernel(const float* __restrict__ p, const float* __restrict__ c_last,
                  const float* __restrict__ featT,
                  const float* __restrict__ w_fc1, const float* __restrict__ b_fc1,
                  const float* __restrict__ w_fc2, const float* __restrict__ b_fc2,
                  const float* __restrict__ w_fcc, const float* __restrict__ b_fcc,
                  float* __restrict__ c_out, float* __restrict__ sums,
                  float* __restrict__ cnt)
{
    extern __shared__ float sm[];
    float* s_a  = sm;                            // 64 x 132 (feat, later c)
    float* s_h1 = sm + 64*SA_STRIDE;             // 64 x 260 (hidden)
    float* s_w  = s_h1 + 64*SH_STRIDE;           // 4096 (weight chunk)
    float* s_cl = s_w + 4096;                    // 64 x 68 (c_last tile)

    const int tid = threadIdx.x;
    const int b   = blockIdx.y;
    const int n0  = blockIdx.x * 64;
    const int i   = tid >> 2;    // point index within block: 0..63
    const int q   = tid & 3;     // channel quarter: 32 floats each
    const int n   = n0 + i;
    const bool act = (n < NPTS);

    // ---- bilinear gather ----
    float xx = 0.f, yy = 0.f;
    if (act) {
        xx = p[((size_t)b * NPTS + n) * 3 + 0];
        yy = p[((size_t)b * NPTS + n) * 3 + 1];
    }
    {
        float px = fminf(fmaxf(xx * 255.f, 0.f), 255.f);
        float py = fminf(fmaxf(yy * 255.f, 0.f), 255.f);
        float x0f = floorf(px), y0f = floorf(py);
        int x0 = (int)x0f, y0 = (int)y0f;
        int x1 = min(x0 + 1, 255), y1 = min(y0 + 1, 255);
        float wx = px - x0f, wy = py - y0f;
        float w00 = (1.f-wx)*(1.f-wy), w01 = wx*(1.f-wy);
        float w10 = (1.f-wx)*wy,       w11 = wx*wy;
        const float* base = featT + ((size_t)b << 23);
        const float4* p00 = (const float4*)(base + ((size_t)((y0<<8)+x0) << 7) + q*32);
        const float4* p01 = (const float4*)(base + ((size_t)((y0<<8)+x1) << 7) + q*32);
        const float4* p10 = (const float4*)(base + ((size_t)((y1<<8)+x0) << 7) + q*32);
        const float4* p11 = (const float4*)(base + ((size_t)((y1<<8)+x1) << 7) + q*32);
        float4* dst = (float4*)(s_a + i*SA_STRIDE + q*32);
#pragma unroll
        for (int c4 = 0; c4 < 8; c4++) {
            float4 a = act ? p00[c4] : make_float4(0,0,0,0);
            float4 bq = act ? p01[c4] : make_float4(0,0,0,0);
            float4 cq = act ? p10[c4] : make_float4(0,0,0,0);
            float4 dq = act ? p11[c4] : make_float4(0,0,0,0);
            float4 r;
            r.x = a.x*w00 + bq.x*w01 + cq.x*w10 + dq.x*w11;
            r.y = a.y*w00 + bq.y*w01 + cq.y*w10 + dq.y*w11;
            r.z = a.z*w00 + bq.z*w01 + cq.z*w10 + dq.z*w11;
            r.w = a.w*w00 + bq.w*w01 + cq.w*w10 + dq.w*w11;
            dst[c4] = r;
        }
    }
    __syncthreads();

    const int cb = tid & 15;   // column lane  (cols cb + 16*j)
    const int pb = tid >> 4;   // point lane   (pts  pb + 16*r)

    // ---- GEMM1: H1[64][256] = relu(feat @ w_fc1 + b_fc1) ----
    u64 accp1[2][16];
#pragma unroll
    for (int rp = 0; rp < 2; rp++)
#pragma unroll
        for (int j = 0; j < 16; j++) accp1[rp][j] = 0ULL;

    for (int kc = 0; kc < 128; kc += 16) {
        __syncthreads();
        for (int idx = tid; idx < 16*256; idx += 256) s_w[idx] = w_fc1[kc*256 + idx];
        __syncthreads();
#pragma unroll
        for (int kk = 0; kk < 16; kk++) {
            float a0 = s_a[(pb     ) * SA_STRIDE + kc + kk];
            float a1 = s_a[(pb + 16) * SA_STRIDE + kc + kk];
            float a2 = s_a[(pb + 32) * SA_STRIDE + kc + kk];
            float a3 = s_a[(pb + 48) * SA_STRIDE + kc + kk];
            u64 ap0 = pack2(a0, a1), ap1 = pack2(a2, a3);
#pragma unroll
            for (int j = 0; j < 16; j++) {
                float wv = s_w[kk*256 + cb + (j << 4)];
                u64 wp = pack2(wv, wv);
                fma2(accp1[0][j], ap0, wp);
                fma2(accp1[1][j], ap1, wp);
            }
        }
    }
    {
#pragma unroll
        for (int j = 0; j < 16; j++) {
            float bv = b_fc1[cb + (j << 4)];
#pragma unroll
            for (int rp = 0; rp < 2; rp++) {
                float lo, hi;
                unpack2(accp1[rp][j], lo, hi);
                s_h1[(pb + ((rp*2    ) << 4)) * SH_STRIDE + cb + (j<<4)] = fmaxf(lo + bv, 0.f);
                s_h1[(pb + ((rp*2 + 1) << 4)) * SH_STRIDE + cb + (j<<4)] = fmaxf(hi + bv, 0.f);
            }
        }
    }

    // ---- GEMM2: C[64][128] = H1 @ w_fc2 ----
    u64 accp2[2][8];
#pragma unroll
    for (int rp = 0; rp < 2; rp++)
#pragma unroll
        for (int j = 0; j < 8; j++) accp2[rp][j] = 0ULL;

    for (int kc = 0; kc < 256; kc += 32) {
        __syncthreads();
        for (int idx = tid; idx < 32*128; idx += 256) s_w[idx] = w_fc2[kc*128 + idx];
        __syncthreads();
#pragma unroll
        for (int kk = 0; kk < 32; kk++) {
            float a0 = s_h1[(pb     ) * SH_STRIDE + kc + kk];
            float a1 = s_h1[(pb + 16) * SH_STRIDE + kc + kk];
            float a2 = s_h1[(pb + 32) * SH_STRIDE + kc + kk];
            float a3 = s_h1[(pb + 48) * SH_STRIDE + kc + kk];
            u64 ap0 = pack2(a0, a1), ap1 = pack2(a2, a3);
#pragma unroll
            for (int j = 0; j < 8; j++) {
                float wv = s_w[kk*128 + cb + (j << 4)];
                u64 wp = pack2(wv, wv);
                fma2(accp2[0][j], ap0, wp);
                fma2(accp2[1][j], ap1, wp);
            }
        }
    }

    // ---- + c_last @ w_fcc ----
    __syncthreads();
    for (int idx = tid; idx < 64*64; idx += 256) {
        int ii = idx >> 6, k = idx & 63;
        s_cl[ii*SCL_STRIDE + k] =
            (n0 + ii < NPTS) ? c_last[((size_t)b * NPTS + n0 + ii) * 64 + k] : 0.f;
    }
    for (int kc = 0; kc < 64; kc += 32) {
        __syncthreads();
        for (int idx = tid; idx < 32*128; idx += 256) s_w[idx] = w_fcc[kc*128 + idx];
        __syncthreads();
#pragma unroll
        for (int kk = 0; kk < 32; kk++) {
            float a0 = s_cl[(pb     ) * SCL_STRIDE + kc + kk];
            float a1 = s_cl[(pb + 16) * SCL_STRIDE + kc + kk];
            float a2 = s_cl[(pb + 32) * SCL_STRIDE + kc + kk];
            float a3 = s_cl[(pb + 48) * SCL_STRIDE + kc + kk];
            u64 ap0 = pack2(a0, a1), ap1 = pack2(a2, a3);
#pragma unroll
            for (int j = 0; j < 8; j++) {
                float wv = s_w[kk*128 + cb + (j << 4)];
                u64 wp = pack2(wv, wv);
                fma2(accp2[0][j], ap0, wp);
                fma2(accp2[1][j], ap1, wp);
            }
        }
    }

    // ---- biases, stage c tile in s_a ----
    {
        __syncthreads();
#pragma unroll
        for (int j = 0; j < 8; j++) {
            float b2v = b_fc2[cb + (j<<4)] + b_fcc[cb + (j<<4)];
#pragma unroll
            for (int rp = 0; rp < 2; rp++) {
                float lo, hi;
                unpack2(accp2[rp][j], lo, hi);
                s_a[(pb + ((rp*2    ) << 4)) * SA_STRIDE + cb + (j<<4)] = lo + b2v;
                s_a[(pb + ((rp*2 + 1) << 4)) * SA_STRIDE + cb + (j<<4)] = hi + b2v;
            }
        }
    }
    __syncthreads();

    // ---- write c (coalesced float4) ----
    {
        size_t cbase4 = ((size_t)b * NPTS + n0) * 32;   // float4 units
#pragma unroll
        for (int qq = 0; qq < 8; qq++) {
            int f4 = tid + qq*256;
            int ii = f4 >> 5;
            int c4 = f4 & 31;
            if (n0 + ii < NPTS) {
                float4 v = *(const float4*)(s_a + ii*SA_STRIDE + (c4 << 2));
                ((float4*)c_out)[cbase4 + (size_t)ii*32 + c4] = v;
            }
        }
    }

    // ---- scatter-add (each point exactly once, 4 threads x 32 ch) ----
    if (act) {
        int sx = min(max((int)(xx * 256.f), 0), 255);
        int sy = min(max((int)(yy * 256.f), 0), 255);
        int seg = sx + (sy << 8);
        float* sp = sums + ((((size_t)b << 16) + seg) << 7) + q * 32;
        const float* src = s_a + i*SA_STRIDE + q * 32;
#pragma unroll
        for (int c = 0; c < 32; c++) atomicAdd(sp + c, src[c]);
        if (q == 0) atomicAdd(cnt + ((size_t)b << 16) + seg, 1.f);
    }
}

// ---------------------------------------------------------------------------
// Normalize scatter sums -> before_pool (NCHW) + fused 2x2 maxpool -> out.
// ---------------------------------------------------------------------------
__global__ __launch_bounds__(256)
void finalize_kernel(const float* __restrict__ sums, const float* __restrict__ cnt,
                     float* __restrict__ before_pool, float* __restrict__ out)
{
    __shared__ float tile[64*129];
    __shared__ float s_inv[64];

    const int tid = threadIdx.x;
    const int b  = blockIdx.z;
    const int yp = blockIdx.y;
    const int xt = blockIdx.x;
    const int x0 = xt * 32, y0 = yp * 2;

    if (tid < 64) {
        int gseg = ((y0 + (tid >> 5)) << 8) + x0 + (tid & 31);
        float c = cnt[((size_t)b << 16) + gseg];
        s_inv[tid] = 1.f / fmaxf(c, 1.f);
    }
    __syncthreads();

#pragma unroll
    for (int qq = 0; qq < 8; qq++) {
        int f4 = tid + qq*256;
        int i  = f4 >> 5;
        int c4 = f4 & 31;
        int gseg = ((y0 + (i >> 5)) << 8) + x0 + (i & 31);
        float4 v = ((const float4*)sums)[((((size_t)b << 16) + gseg) << 5) + c4];
        float inv = s_inv[i];
        float* tp = tile + i*129 + (c4 << 2);
        tp[0] = v.x * inv; tp[1] = v.y * inv; tp[2] = v.z * inv; tp[3] = v.w * inv;
    }
    __syncthreads();

    const int xi = tid & 31, cg = tid >> 5;
#pragma unroll
    for (int cc = 0; cc < 16; cc++) {
        int ch = cg + (cc << 3);
        float r0 = tile[xi * 129 + ch];
        float r1 = tile[(32 + xi) * 129 + ch];
        size_t bp = ((size_t)(b*128 + ch)) << 16;
        before_pool[bp + ((size_t)y0 << 8) + x0 + xi]       = r0;
        before_pool[bp + ((size_t)(y0+1) << 8) + x0 + xi]   = r1;
        if (xi < 16) {
            float m0 = fmaxf(tile[(2*xi) * 129 + ch],      tile[(2*xi + 1) * 129 + ch]);
            float m1 = fmaxf(tile[(32 + 2*xi) * 129 + ch], tile[(33 + 2*xi) * 129 + ch]);
            out[(((size_t)(b*128 + ch)) << 14) + (yp << 7) + (x0 >> 1) + xi] = fmaxf(m0, m1);
        }
    }
}

// ---------------------------------------------------------------------------
// launch
// ---------------------------------------------------------------------------
extern "C" void kernel_launch(void* const* d_in, const int* in_sizes, int n_in,
                              void* d_out, int out_size)
{
    const float* p      = (const float*)d_in[0];
    const float* x_xy   = (const float*)d_in[1];
    const float* x2     = (const float*)d_in[2];
    const float* c_last = (const float*)d_in[3];
    const float* w1     = (const float*)d_in[4];
    const float* b1     = (const float*)d_in[5];
    const float* w2     = (const float*)d_in[6];
    const float* b2     = (const float*)d_in[7];
    const float* w1x1   = (const float*)d_in[8];
    const float* b1x1   = (const float*)d_in[9];
    const float* wfc1   = (const float*)d_in[10];
    const float* bfc1   = (const float*)d_in[11];
    const float* wfc2   = (const float*)d_in[12];
    const float* bfc2   = (const float*)d_in[13];
    const float* wfcc   = (const float*)d_in[14];
    const float* bfcc   = (const float*)d_in[15];

    float* out        = (float*)d_out;
    float* out_pool   = out + OFF_POOL;
    float* out_bp     = out + OFF_BP;
    float* out_xafter = out + OFF_XAFTER;
    float* out_c      = out + OFF_C;

    float *h1, *featT, *sums, *cntp;
    cudaGetSymbolAddress((void**)&h1,    g_h1);
    cudaGetSymbolAddress((void**)&featT, g_featT);
    cudaGetSymbolAddress((void**)&sums,  g_sums);
    cudaGetSymbolAddress((void**)&cntp,  g_cnt);

    // zero scatter scratch (re-done every launch / graph replay)
    zero_kernel<<<(4194304 + 255) / 256, 256>>>(sums, 4194304);
    zero_kernel<<<(32768 + 255) / 256, 256>>>(cntp, 32768);

    // conv1: x_xy -> h1 (relu)
    conv3x3_kernel<64, false><<<dim3(8, 8, 32), 256>>>(
        x_xy, w1, b1, nullptr, nullptr, nullptr, h1, nullptr);

    // conv2 + fused 1x1: h1 -> x_after (NCHW in d_out) + featT (NHWC scratch)
    conv3x3_kernel<128, true><<<dim3(8, 8, 32), 256>>>(
        h1, w2, b2, x2, w1x1, b1x1, out_xafter, featT);

    // point pipeline
    const int pk_smem = PK_SMEM_FLOATS * 4;
    cudaFuncSetAttribute(point_kernel, cudaFuncAttributeMaxDynamicSharedMemorySize,
                         pk_smem);
    point_kernel<<<dim3((NPTS + 63) / 64, 2), 256, pk_smem>>>(
        p, c_last, featT, wfc1, bfc1, wfc2, bfc2, wfcc, bfcc,
        out_c, sums, cntp);

    // normalize + maxpool
    finalize_kernel<<<dim3(8, 128, 2), 256>>>(sums, cntp, out_bp, out_pool);
}

// round 9
// speedup vs baseline: 2.0751x; 2.0751x over previous
#include <cuda_runtime.h>
#include <cuda_bf16.h>
#include <cstdint>

// ---------------------------------------------------------------------------
#define BB   2
#define NPTS 100000
#define PW   258
#define PPIX (258*258)

#define OFF_POOL   0
#define SZ_POOL    (2*128*128*128)
#define OFF_BP     (SZ_POOL)
#define SZ_BP      (2*128*256*256)
#define OFF_XAFTER (OFF_BP + SZ_BP)
#define OFF_C      (OFF_XAFTER + SZ_BP)

typedef unsigned long long u64;
typedef unsigned int u32;

__device__ __forceinline__ void bsplit(float x, __nv_bfloat16& h, __nv_bfloat16& l) {
    h = __float2bfloat16(x);
    l = __float2bfloat16(x - __bfloat162float(h));
}
__device__ __forceinline__ u32 packbf(__nv_bfloat16 a, __nv_bfloat16 b) {
    return (u32)__bfloat16_as_ushort(a) | ((u32)__bfloat16_as_ushort(b) << 16);
}

#define MMA_BF16(c, a, bf) \
    asm volatile("mma.sync.aligned.m16n8k16.row.col.f32.bf16.bf16.f32 " \
        "{%0,%1,%2,%3}, {%4,%5,%6,%7}, {%8,%9}, {%0,%1,%2,%3};" \
        : "+f"((c)[0]), "+f"((c)[1]), "+f"((c)[2]), "+f"((c)[3]) \
        : "r"((a)[0]), "r"((a)[1]), "r"((a)[2]), "r"((a)[3]), \
          "r"((bf)[0]), "r"((bf)[1]))

// ---------------------------------------------------------------------------
// Scratch (device globals)
// ---------------------------------------------------------------------------
__device__ __nv_bfloat16 g_n1h[2*PPIX*64],  g_n1l[2*PPIX*64];
__device__ __nv_bfloat16 g_x2h[2*PPIX*64],  g_x2l[2*PPIX*64];
__device__ __nv_bfloat16 g_c2h[4*PPIX*64],  g_c2l[4*PPIX*64];
__device__ __nv_bfloat16 g_w1h[9*128*64],   g_w1l[9*128*64];
__device__ __nv_bfloat16 g_w2h[18*128*64],  g_w2l[18*128*64];
__device__ __nv_bfloat16 g_wxh[128*64],     g_wxl[128*64];
__device__ float g_featT[2*65536*128];
__device__ float g_sums[2*65536*128];
__device__ float g_cnt[2*65536];

// ---------------------------------------------------------------------------
__global__ void zero_kernel(float* a, int n4) {
    int i = blockIdx.x * blockDim.x + threadIdx.x;
    if (i < n4) ((float4*)a)[i] = make_float4(0.f, 0.f, 0.f, 0.f);
}

// weight split/reorder: src [128][I][T] -> dst[(tap*(I/64)+ch)*128 + o][64]
__global__ void wsplit_kernel(const float* __restrict__ src,
                              __nv_bfloat16* __restrict__ dh, __nv_bfloat16* __restrict__ dl,
                              int I, int T) {
    int total = 128 * I * T;
    int idx = blockIdx.x * blockDim.x + threadIdx.x;
    if (idx >= total) return;
    int o = idx / (I * T);
    int rem = idx - o * (I * T);
    int i = rem / T;
    int tap = rem - i * T;
    int ch = i >> 6, c = i & 63;
    int d = ((tap * (I >> 6) + ch) * 128 + o) * 64 + c;
    bsplit(src[idx], dh[d], dl[d]);
}

// NCHW fp32 -> padded NHWC bf16 hi/lo (CIN=64)
__global__ __launch_bounds__(256)
void nhwc_kernel(const float* __restrict__ src,
                 __nv_bfloat16* __restrict__ dh, __nv_bfloat16* __restrict__ dl) {
    __shared__ float s[32][33];
    int t = threadIdx.x, tx = t & 31, ty = t >> 5;
    int x0 = blockIdx.x * 32, c0 = blockIdx.y * 32;
    int y = blockIdx.z & 255, b = blockIdx.z >> 8;
#pragma unroll
    for (int i = 0; i < 4; i++) {
        int c = c0 + ty + i * 8;
        s[ty + i * 8][tx] = src[(((size_t)b * 64 + c) << 16) + (y << 8) + x0 + tx];
    }
    __syncthreads();
#pragma unroll
    for (int i = 0; i < 4; i++) {
        int x = x0 + ty + i * 8;
        float v = s[tx][ty + i * 8];
        size_t d = ((size_t)b * PPIX + (size_t)(y + 1) * PW + (x + 1)) * 64 + c0 + tx;
        bsplit(v, dh[d], dl[d]);
    }
}

// ---------------------------------------------------------------------------
// mma.sync conv kernel.  Block tile: 128 px (one row seg) x 128 couts.
// 8 warps: (wid&1)->64px, (wid>>1)->32oc.  Per group: stage Ah/Al/Bh/Bl
// (each 128x64 bf16, smem rows padded to 72 bf16), then 3 split-combos x
// 4 k-steps of m16n8k16.  Plain device functions (no lambdas).
// ---------------------------------------------------------------------------
#define SMEM_A_H 0
#define SMEM_A_L 18432
#define SMEM_B_H 36864
#define SMEM_B_L 55296
#define CONV_SMEM 73728

__device__ __forceinline__ void stage4(char* smem, int tid,
                                       const __nv_bfloat16* sAh, const __nv_bfloat16* sAl,
                                       const __nv_bfloat16* sBh, const __nv_bfloat16* sBl)
{
    const __nv_bfloat16* srcs[4] = { sAh, sAl, sBh, sBl };
#pragma unroll
    for (int w_ = 0; w_ < 4; w_++) {
        const uint4* s4 = (const uint4*)srcs[w_];
        char* d0 = smem + w_ * 18432;
#pragma unroll
        for (int u = 0; u < 4; u++) {
            int unit = tid + u * 256;           // 1024 x 16B = 16KB
            int row = unit >> 3, q = unit & 7;
            *(uint4*)(d0 + row * 144 + q * 16) = s4[unit];
        }
    }
}

__device__ __forceinline__ void mma_group(const char* smem, int M0, int N0,
                                          int lq, int lr, float (&C)[4][4][4])
{
#pragma unroll
    for (int ks = 0; ks < 4; ks++) {
        const int kc2 = (ks * 16 + lr) * 2;     // byte offset of k element
        u32 bh[4][2], bl[4][2];
#pragma unroll
        for (int nt = 0; nt < 4; nt++) {
            int n = N0 + nt * 8 + lq;
            bh[nt][0] = *(const u32*)(smem + SMEM_B_H + n * 144 + kc2);
            bh[nt][1] = *(const u32*)(smem + SMEM_B_H + n * 144 + kc2 + 16);
            bl[nt][0] = *(const u32*)(smem + SMEM_B_L + n * 144 + kc2);
            bl[nt][1] = *(const u32*)(smem + SMEM_B_L + n * 144 + kc2 + 16);
        }
#pragma unroll
        for (int mt = 0; mt < 4; mt++) {
            int r = M0 + mt * 16 + lq;
            u32 ah[4], al[4];
            ah[0] = *(const u32*)(smem + SMEM_A_H + r * 144 + kc2);
            ah[1] = *(const u32*)(smem + SMEM_A_H + (r + 8) * 144 + kc2);
            ah[2] = *(const u32*)(smem + SMEM_A_H + r * 144 + kc2 + 16);
            ah[3] = *(const u32*)(smem + SMEM_A_H + (r + 8) * 144 + kc2 + 16);
            al[0] = *(const u32*)(smem + SMEM_A_L + r * 144 + kc2);
            al[1] = *(const u32*)(smem + SMEM_A_L + (r + 8) * 144 + kc2);
            al[2] = *(const u32*)(smem + SMEM_A_L + r * 144 + kc2 + 16);
            al[3] = *(const u32*)(smem + SMEM_A_L + (r + 8) * 144 + kc2 + 16);
#pragma unroll
            for (int nt = 0; nt < 4; nt++) {
                MMA_BF16(C[mt][nt], ah, bh[nt]);
                MMA_BF16(C[mt][nt], ah, bl[nt]);
                MMA_BF16(C[mt][nt], al, bh[nt]);
            }
        }
    }
}

template<bool IS2>
__global__ __launch_bounds__(256)
void conv_mma_kernel(const __nv_bfloat16* __restrict__ Ah_base,
                     const __nv_bfloat16* __restrict__ Al_base,
                     const __nv_bfloat16* __restrict__ Bh_w,
                     const __nv_bfloat16* __restrict__ Bl_w,
                     const __nv_bfloat16* __restrict__ X2h,
                     const __nv_bfloat16* __restrict__ X2l,
                     const __nv_bfloat16* __restrict__ W1h,
                     const __nv_bfloat16* __restrict__ W1l,
                     const float* __restrict__ bias1,
                     const float* __restrict__ bias2,
                     float* __restrict__ out_nchw,
                     float* __restrict__ out_nhwc,
                     __nv_bfloat16* __restrict__ Oh,
                     __nv_bfloat16* __restrict__ Ol)
{
    constexpr int CC = IS2 ? 2 : 1;
    constexpr int NG = 9 * CC;
    extern __shared__ __align__(16) char smem[];
    __shared__ float s_b1[128];
    __shared__ float s_b2[128];

    const int tid = threadIdx.x;
    const int lane = tid & 31, wid = tid >> 5;
    const int b  = blockIdx.x >> 9;
    const int rr = blockIdx.x & 511;
    const int y  = rr >> 1;
    const int x0 = (rr & 1) << 7;

    const int M0 = (wid & 1) * 64;
    const int N0 = (wid >> 1) * 32;
    const int lq = lane >> 2;          // 0..7
    const int lr = (lane & 3) * 2;     // 0,2,4,6

    if (tid < 128) { s_b1[tid] = bias1[tid]; s_b2[tid] = IS2 ? bias2[tid] : 0.f; }

    float C[4][4][4];
#pragma unroll
    for (int mt = 0; mt < 4; mt++)
#pragma unroll
        for (int nt = 0; nt < 4; nt++)
#pragma unroll
            for (int r = 0; r < 4; r++) C[mt][nt][r] = 0.f;

    // ---- conv groups ----
    for (int g = 0; g < NG; g++) {
        int tap = g / CC, ch = g - tap * CC;
        int dy = tap / 3, dx = tap - dy * 3;
        size_t pbase = (((size_t)b * CC + ch) * PPIX + (size_t)(y + dy) * PW + (x0 + dx)) * 64;
        size_t wb = (size_t)g * 8192;
        __syncthreads();
        stage4(smem, tid, Ah_base + pbase, Al_base + pbase, Bh_w + wb, Bl_w + wb);
        __syncthreads();
        mma_group(smem, M0, N0, lq, lr, C);
    }

    // ---- bias + relu (in registers) ----
#pragma unroll
    for (int mt = 0; mt < 4; mt++)
#pragma unroll
        for (int nt = 0; nt < 4; nt++) {
            int co = N0 + nt * 8 + lr;
            float b0 = s_b1[co], b1v = s_b1[co + 1];
            C[mt][nt][0] = fmaxf(C[mt][nt][0] + b0, 0.f);
            C[mt][nt][1] = fmaxf(C[mt][nt][1] + b1v, 0.f);
            C[mt][nt][2] = fmaxf(C[mt][nt][2] + b0, 0.f);
            C[mt][nt][3] = fmaxf(C[mt][nt][3] + b1v, 0.f);
        }

    if (IS2) {
        // ---- 1x1 fuse group into same accumulators ----
        size_t pbase = ((size_t)b * PPIX + (size_t)(y + 1) * PW + (x0 + 1)) * 64;
        __syncthreads();
        stage4(smem, tid, X2h + pbase, X2l + pbase, W1h, W1l);
        __syncthreads();
        mma_group(smem, M0, N0, lq, lr, C);
#pragma unroll
        for (int mt = 0; mt < 4; mt++)
#pragma unroll
            for (int nt = 0; nt < 4; nt++) {
                int co = N0 + nt * 8 + lr;
                C[mt][nt][0] += s_b2[co];
                C[mt][nt][1] += s_b2[co + 1];
                C[mt][nt][2] += s_b2[co];
                C[mt][nt][3] += s_b2[co + 1];
            }

        // ---- epilogue: fp32 tile [128px][132] in smem ----
        __syncthreads();
        float* st = (float*)smem;
#pragma unroll
        for (int mt = 0; mt < 4; mt++)
#pragma unroll
            for (int nt = 0; nt < 4; nt++) {
                int px = M0 + mt * 16 + lq;
                int co = N0 + nt * 8 + lr;
                st[px * 132 + co]           = C[mt][nt][0];
                st[px * 132 + co + 1]       = C[mt][nt][1];
                st[(px + 8) * 132 + co]     = C[mt][nt][2];
                st[(px + 8) * 132 + co + 1] = C[mt][nt][3];
            }
        __syncthreads();
        // featT (NHWC fp32): 128 px x 512B, fully coalesced
#pragma unroll
        for (int u = 0; u < 16; u++) {
            int idx = tid + u * 256;      // 4096 uint4
            int px = idx >> 5, q = idx & 31;
            *(uint4*)(out_nhwc + ((((size_t)b << 16) + ((size_t)y << 8) + x0 + px) << 7) + q * 4)
                = *(const uint4*)((const char*)st + px * 528 + q * 16);
        }
        // x_after (NCHW fp32): transpose read, coalesced write
#pragma unroll
        for (int u = 0; u < 16; u++) {
            int idx = tid + u * 256;      // 4096: c x xq
            int c = idx >> 5, xq = idx & 31;
            float4 v = make_float4(st[(xq*4+0)*132 + c], st[(xq*4+1)*132 + c],
                                   st[(xq*4+2)*132 + c], st[(xq*4+3)*132 + c]);
            *(float4*)(out_nchw + (((size_t)b * 128 + c) << 16) + ((size_t)y << 8) + x0 + xq * 4) = v;
        }
    } else {
        // ---- epilogue: bf16 split planes for conv2 ----
        __syncthreads();
#pragma unroll
        for (int mt = 0; mt < 4; mt++)
#pragma unroll
            for (int nt = 0; nt < 4; nt++) {
                int px = M0 + mt * 16 + lq;
                int co = N0 + nt * 8 + lr;
#pragma unroll
                for (int hh = 0; hh < 2; hh++) {
                    int p = px + hh * 8;
                    float v0 = C[mt][nt][hh * 2], v1 = C[mt][nt][hh * 2 + 1];
                    __nv_bfloat16 h0, l0, h1, l1;
                    bsplit(v0, h0, l0);
                    bsplit(v1, h1, l1);
                    *(u32*)(smem + p * 272 + co * 2)         = packbf(h0, h1);
                    *(u32*)(smem + 34816 + p * 272 + co * 2) = packbf(l0, l1);
                }
            }
        __syncthreads();
        size_t prow = (size_t)(y + 1) * PW + (x0 + 1);
#pragma unroll
        for (int u = 0; u < 8; u++) {
            int idx = tid + u * 256;       // 2048 uint4
            int px = idx >> 4, q = idx & 15;
            int chh = q >> 3, qq = q & 7;
            size_t doff = (((size_t)b * 2 + chh) * PPIX + prow + px) * 64 + qq * 8;
            *(uint4*)(Oh + doff) = *(const uint4*)(smem + px * 272 + chh * 128 + qq * 16);
            *(uint4*)(Ol + doff) = *(const uint4*)(smem + 34816 + px * 272 + chh * 128 + qq * 16);
        }
    }
}

// ---------------------------------------------------------------------------
// Point kernel (R2 scalar): gather -> MLP -> c write -> scatter-add
// ---------------------------------------------------------------------------
#define SA_STRIDE 132
#define SH_STRIDE 260
#define SCL_STRIDE 68
#define PK_SMEM_FLOATS (64*SA_STRIDE + 64*SH_STRIDE + 4096 + 64*SCL_STRIDE)

__global__ __launch_bounds__(256, 1)
void point_kernel(const float* __restrict__ p, const float* __restrict__ c_last,
                  const float* __restrict__ featT,
                  const float* __restrict__ w_fc1, const float* __restrict__ b_fc1,
                  const float* __restrict__ w_fc2, const float* __restrict__ b_fc2,
                  const float* __restrict__ w_fcc, const float* __restrict__ b_fcc,
                  float* __restrict__ c_out, float* __restrict__ sums,
                  float* __restrict__ cnt)
{
    extern __shared__ float sm[];
    float* s_a  = sm;
    float* s_h1 = sm + 64*SA_STRIDE;
    float* s_w  = s_h1 + 64*SH_STRIDE;
    float* s_cl = s_w + 4096;

    const int tid = threadIdx.x;
    const int b   = blockIdx.y;
    const int n0  = blockIdx.x * 64;
    const int i   = tid >> 2;
    const int q   = tid & 3;
    const int n   = n0 + i;
    const bool act = (n < NPTS);

    float xx = 0.f, yy = 0.f;
    if (act) {
        xx = p[((size_t)b * NPTS + n) * 3 + 0];
        yy = p[((size_t)b * NPTS + n) * 3 + 1];
    }
    {
        float px = fminf(fmaxf(xx * 255.f, 0.f), 255.f);
        float py = fminf(fmaxf(yy * 255.f, 0.f), 255.f);
        float x0f = floorf(px), y0f = floorf(py);
        int x0 = (int)x0f, y0 = (int)y0f;
        int x1 = min(x0 + 1, 255), y1 = min(y0 + 1, 255);
        float wx = px - x0f, wy = py - y0f;
        float w00 = (1.f-wx)*(1.f-wy), w01 = wx*(1.f-wy);
        float w10 = (1.f-wx)*wy,       w11 = wx*wy;
        const float* base = featT + ((size_t)b << 23);
        const float4* p00 = (const float4*)(base + ((size_t)((y0<<8)+x0) << 7) + q*32);
        const float4* p01 = (const float4*)(base + ((size_t)((y0<<8)+x1) << 7) + q*32);
        const float4* p10 = (const float4*)(base + ((size_t)((y1<<8)+x0) << 7) + q*32);
        const float4* p11 = (const float4*)(base + ((size_t)((y1<<8)+x1) << 7) + q*32);
        float4* dst = (float4*)(s_a + i*SA_STRIDE + q*32);
#pragma unroll
        for (int c4 = 0; c4 < 8; c4++) {
            float4 a = act ? p00[c4] : make_float4(0,0,0,0);
            float4 bq = act ? p01[c4] : make_float4(0,0,0,0);
            float4 cq = act ? p10[c4] : make_float4(0,0,0,0);
            float4 dq = act ? p11[c4] : make_float4(0,0,0,0);
            float4 r;
            r.x = a.x*w00 + bq.x*w01 + cq.x*w10 + dq.x*w11;
            r.y = a.y*w00 + bq.y*w01 + cq.y*w10 + dq.y*w11;
            r.z = a.z*w00 + bq.z*w01 + cq.z*w10 + dq.z*w11;
            r.w = a.w*w00 + bq.w*w01 + cq.w*w10 + dq.w*w11;
            dst[c4] = r;
        }
    }
    __syncthreads();

    const int cb = tid & 15;
    const int pb = tid >> 4;

    float acc1[4][16];
#pragma unroll
    for (int r = 0; r < 4; r++)
#pragma unroll
        for (int j = 0; j < 16; j++) acc1[r][j] = 0.f;

    for (int kc = 0; kc < 128; kc += 16) {
        __syncthreads();
        for (int idx = tid; idx < 16*256; idx += 256) s_w[idx] = w_fc1[kc*256 + idx];
        __syncthreads();
#pragma unroll
        for (int kk = 0; kk < 16; kk++) {
            float a[4];
#pragma unroll
            for (int r = 0; r < 4; r++) a[r] = s_a[(pb + (r<<4)) * SA_STRIDE + kc + kk];
#pragma unroll
            for (int jh = 0; jh < 2; jh++) {
                float wv[8];
#pragma unroll
                for (int j = 0; j < 8; j++) wv[j] = s_w[kk*256 + cb + ((jh*8 + j) << 4)];
#pragma unroll
                for (int r = 0; r < 4; r++)
#pragma unroll
                    for (int j = 0; j < 8; j++) acc1[r][jh*8 + j] += a[r] * wv[j];
            }
        }
    }
    {
        float b1v[16];
#pragma unroll
        for (int j = 0; j < 16; j++) b1v[j] = b_fc1[cb + (j << 4)];
#pragma unroll
        for (int r = 0; r < 4; r++)
#pragma unroll
            for (int j = 0; j < 16; j++)
                s_h1[(pb + (r<<4)) * SH_STRIDE + cb + (j<<4)] = fmaxf(acc1[r][j] + b1v[j], 0.f);
    }

    float acc2[4][8];
#pragma unroll
    for (int r = 0; r < 4; r++)
#pragma unroll
        for (int j = 0; j < 8; j++) acc2[r][j] = 0.f;

    for (int kc = 0; kc < 256; kc += 32) {
        __syncthreads();
        for (int idx = tid; idx < 32*128; idx += 256) s_w[idx] = w_fc2[kc*128 + idx];
        __syncthreads();
#pragma unroll
        for (int kk = 0; kk < 32; kk++) {
            float a[4];
#pragma unroll
            for (int r = 0; r < 4; r++) a[r] = s_h1[(pb + (r<<4)) * SH_STRIDE + kc + kk];
            float wv[8];
#pragma unroll
            for (int j = 0; j < 8; j++) wv[j] = s_w[kk*128 + cb + (j<<4)];
#pragma unroll
            for (int r = 0; r < 4; r++)
#pragma unroll
                for (int j = 0; j < 8; j++) acc2[r][j] += a[r] * wv[j];
        }
    }

    __syncthreads();
    for (int idx = tid; idx < 64*64; idx += 256) {
        int ii = idx >> 6, k = idx & 63;
        s_cl[ii*SCL_STRIDE + k] =
            (n0 + ii < NPTS) ? c_last[((size_t)b * NPTS + n0 + ii) * 64 + k] : 0.f;
    }
    for (int kc = 0; kc < 64; kc += 32) {
        __syncthreads();
        for (int idx = tid; idx < 32*128; idx += 256) s_w[idx] = w_fcc[kc*128 + idx];
        __syncthreads();
#pragma unroll
        for (int kk = 0; kk < 32; kk++) {
            float a[4];
#pragma unroll
            for (int r = 0; r < 4; r++) a[r] = s_cl[(pb + (r<<4)) * SCL_STRIDE + kc + kk];
            float wv[8];
#pragma unroll
            for (int j = 0; j < 8; j++) wv[j] = s_w[kk*128 + cb + (j<<4)];
#pragma unroll
            for (int r = 0; r < 4; r++)
#pragma unroll
                for (int j = 0; j < 8; j++) acc2[r][j] += a[r] * wv[j];
        }
    }

    {
        float b2v[8];
#pragma unroll
        for (int j = 0; j < 8; j++) b2v[j] = b_fc2[cb + (j<<4)] + b_fcc[cb + (j<<4)];
        __syncthreads();
#pragma unroll
        for (int r = 0; r < 4; r++)
#pragma unroll
            for (int j = 0; j < 8; j++)
                s_a[(pb + (r<<4)) * SA_STRIDE + cb + (j<<4)] = acc2[r][j] + b2v[j];
    }
    __syncthreads();

    {
        size_t cbase4 = ((size_t)b * NPTS + n0) * 32;
#pragma unroll
        for (int qq = 0; qq < 8; qq++) {
            int f4 = tid + qq*256;
            int ii = f4 >> 5;
            int c4 = f4 & 31;
            if (n0 + ii < NPTS) {
                float4 v = *(const float4*)(s_a + ii*SA_STRIDE + (c4 << 2));
                ((float4*)c_out)[cbase4 + (size_t)ii*32 + c4] = v;
            }
        }
    }

    if (act) {
        int sx = min(max((int)(xx * 256.f), 0), 255);
        int sy = min(max((int)(yy * 256.f), 0), 255);
        int seg = sx + (sy << 8);
        float* sp = sums + ((((size_t)b << 16) + seg) << 7) + q * 32;
        const float* src = s_a + i*SA_STRIDE + q * 32;
#pragma unroll
        for (int c = 0; c < 32; c++) atomicAdd(sp + c, src[c]);
        if (q == 0) atomicAdd(cnt + ((size_t)b << 16) + seg, 1.f);
    }
}

// ---------------------------------------------------------------------------
__global__ __launch_bounds__(256)
void finalize_kernel(const float* __restrict__ sums, const float* __restrict__ cnt,
                     float* __restrict__ before_pool, float* __restrict__ out)
{
    __shared__ float tile[64*129];
    __shared__ float s_inv[64];

    const int tid = threadIdx.x;
    const int b  = blockIdx.z;
    const int yp = blockIdx.y;
    const int xt = blockIdx.x;
    const int x0 = xt * 32, y0 = yp * 2;

    if (tid < 64) {
        int gseg = ((y0 + (tid >> 5)) << 8) + x0 + (tid & 31);
        float c = cnt[((size_t)b << 16) + gseg];
        s_inv[tid] = 1.f / fmaxf(c, 1.f);
    }
    __syncthreads();

#pragma unroll
    for (int qq = 0; qq < 8; qq++) {
        int f4 = tid + qq*256;
        int i  = f4 >> 5;
        int c4 = f4 & 31;
        int gseg = ((y0 + (i >> 5)) << 8) + x0 + (i & 31);
        float4 v = ((const float4*)sums)[((((size_t)b << 16) + gseg) << 5) + c4];
        float inv = s_inv[i];
        float* tp = tile + i*129 + (c4 << 2);
        tp[0] = v.x * inv; tp[1] = v.y * inv; tp[2] = v.z * inv; tp[3] = v.w * inv;
    }
    __syncthreads();

    const int xi = tid & 31, cg = tid >> 5;
#pragma unroll
    for (int cc = 0; cc < 16; cc++) {
        int ch = cg + (cc << 3);
        float r0 = tile[xi * 129 + ch];
        float r1 = tile[(32 + xi) * 129 + ch];
        size_t bp = ((size_t)(b*128 + ch)) << 16;
        before_pool[bp + ((size_t)y0 << 8) + x0 + xi]       = r0;
        before_pool[bp + ((size_t)(y0+1) << 8) + x0 + xi]   = r1;
        if (xi < 16) {
            float m0 = fmaxf(tile[(2*xi) * 129 + ch],      tile[(2*xi + 1) * 129 + ch]);
            float m1 = fmaxf(tile[(32 + 2*xi) * 129 + ch], tile[(33 + 2*xi) * 129 + ch]);
            out[(((size_t)(b*128 + ch)) << 14) + (yp << 7) + (x0 >> 1) + xi] = fmaxf(m0, m1);
        }
    }
}

// ---------------------------------------------------------------------------
extern "C" void kernel_launch(void* const* d_in, const int* in_sizes, int n_in,
                              void* d_out, int out_size)
{
    const float* p      = (const float*)d_in[0];
    const float* x_xy   = (const float*)d_in[1];
    const float* x2     = (const float*)d_in[2];
    const float* c_last = (const float*)d_in[3];
    const float* w1     = (const float*)d_in[4];
    const float* b1     = (const float*)d_in[5];
    const float* w2     = (const float*)d_in[6];
    const float* b2     = (const float*)d_in[7];
    const float* w1x1   = (const float*)d_in[8];
    const float* b1x1   = (const float*)d_in[9];
    const float* wfc1   = (const float*)d_in[10];
    const float* bfc1   = (const float*)d_in[11];
    const float* wfc2   = (const float*)d_in[12];
    const float* bfc2   = (const float*)d_in[13];
    const float* wfcc   = (const float*)d_in[14];
    const float* bfcc   = (const float*)d_in[15];

    float* out        = (float*)d_out;
    float* out_pool   = out + OFF_POOL;
    float* out_bp     = out + OFF_BP;
    float* out_xafter = out + OFF_XAFTER;
    float* out_c      = out + OFF_C;

    __nv_bfloat16 *n1h, *n1l, *x2h, *x2l, *c2h, *c2l;
    __nv_bfloat16 *w1h, *w1l, *w2h, *w2l, *wxh, *wxl;
    float *featT, *sums, *cntp;
    cudaGetSymbolAddress((void**)&n1h, g_n1h);  cudaGetSymbolAddress((void**)&n1l, g_n1l);
    cudaGetSymbolAddress((void**)&x2h, g_x2h);  cudaGetSymbolAddress((void**)&x2l, g_x2l);
    cudaGetSymbolAddress((void**)&c2h, g_c2h);  cudaGetSymbolAddress((void**)&c2l, g_c2l);
    cudaGetSymbolAddress((void**)&w1h, g_w1h);  cudaGetSymbolAddress((void**)&w1l, g_w1l);
    cudaGetSymbolAddress((void**)&w2h, g_w2h);  cudaGetSymbolAddress((void**)&w2l, g_w2l);
    cudaGetSymbolAddress((void**)&wxh, g_wxh);  cudaGetSymbolAddress((void**)&wxl, g_wxl);
    cudaGetSymbolAddress((void**)&featT, g_featT);
    cudaGetSymbolAddress((void**)&sums,  g_sums);
    cudaGetSymbolAddress((void**)&cntp,  g_cnt);

    // zero scatter scratch + halo planes
    zero_kernel<<<(4194304 + 255) / 256, 256>>>(sums, 4194304);
    zero_kernel<<<(32768 + 255) / 256, 256>>>(cntp, 32768);
    {
        int n1f4 = (int)((size_t)2*PPIX*64*2 / 16);
        int c2f4 = (int)((size_t)4*PPIX*64*2 / 16);
        zero_kernel<<<(n1f4 + 255)/256, 256>>>((float*)n1h, n1f4);
        zero_kernel<<<(n1f4 + 255)/256, 256>>>((float*)n1l, n1f4);
        zero_kernel<<<(c2f4 + 255)/256, 256>>>((float*)c2h, c2f4);
        zero_kernel<<<(c2f4 + 255)/256, 256>>>((float*)c2l, c2f4);
    }

    // weight splits
    wsplit_kernel<<<(128*64*9 + 255)/256, 256>>>(w1, w1h, w1l, 64, 9);
    wsplit_kernel<<<(128*128*9 + 255)/256, 256>>>(w2, w2h, w2l, 128, 9);
    wsplit_kernel<<<(128*64 + 255)/256, 256>>>(w1x1, wxh, wxl, 64, 1);

    // input conversions
    nhwc_kernel<<<dim3(8, 2, 512), 256>>>(x_xy, n1h, n1l);
    nhwc_kernel<<<dim3(8, 2, 512), 256>>>(x2,   x2h, x2l);

    // mma convs
    cudaFuncSetAttribute(conv_mma_kernel<false>,
                         cudaFuncAttributeMaxDynamicSharedMemorySize, CONV_SMEM);
    cudaFuncSetAttribute(conv_mma_kernel<true>,
                         cudaFuncAttributeMaxDynamicSharedMemorySize, CONV_SMEM);
    conv_mma_kernel<false><<<1024, 256, CONV_SMEM>>>(
        n1h, n1l, w1h, w1l, nullptr, nullptr, nullptr, nullptr,
        b1, nullptr, nullptr, nullptr, c2h, c2l);
    conv_mma_kernel<true><<<1024, 256, CONV_SMEM>>>(
        c2h, c2l, w2h, w2l, x2h, x2l, wxh, wxl,
        b2, b1x1, out_xafter, featT, nullptr, nullptr);

    // point pipeline
    const int pk_smem = PK_SMEM_FLOATS * 4;
    cudaFuncSetAttribute(point_kernel, cudaFuncAttributeMaxDynamicSharedMemorySize,
                         pk_smem);
    point_kernel<<<dim3((NPTS + 63) / 64, 2), 256, pk_smem>>>(
        p, c_last, featT, wfc1, bfc1, wfc2, bfc2, wfcc, bfcc,
        out_c, sums, cntp);

    // normalize + maxpool
    finalize_kernel<<<dim3(8, 128, 2), 256>>>(sums, cntp, out_bp, out_pool);
}